// round 17
// baseline (speedup 1.0000x reference)
#include <cuda_runtime.h>
#include <math.h>

// Shapes
//   amplitudes, frequencies : [8, 250, 100] f32
//   out = concat( amp_env [8, 64000, 100], freq_env [8, 250, 100] )  f32
#define B            8
#define FRAMES       250
#define CH           100
#define CH4          (CH / 4)                 // 25 float4 groups
#define CTRL_ELEMS   (B * FRAMES * CH)        // 200000
#define T_OUT        64000
#define HOP          256                      // 64000 / 250
#define ENV_ELEMS    (B * T_OUT * CH)         // 51200000
#define SEGS         (B * FRAMES)             // 2000 segments
#define SEG_VEC4     (HOP * CH4)              // 6400 float4 per segment
#define UP_THREADS   400                      // 16 rows x 25 float4-groups
#define STORES       16                       // float4 stores per thread

// ---------------------------------------------------------------------------
// Controls math for one raw (amp, freq) element with harmonic index h (1-based):
//   freq = 440 * 2^((sigmoid(f)*MIDI_MAX - 69)/12)
//   amp  = (2*sigmoid(a)^ln(10) + 1e-7) * ((freq*h < SR/2) + 1e-4)
// Fast intrinsics: rel err ~2^-21, orders below the 1e-3 gate (verified
// rel_err 2.3e-7 in R16 with the same chain).
// ---------------------------------------------------------------------------
__device__ __forceinline__ void ctrl1(float a, float f, float h,
                                      float& amp, float& freq) {
    const float LOG10_F  = 2.302585092994046f;
    const float MIDI_MAX = 119.21309485364912f;
    const float NYQ      = 22050.0f;

    float uf = 1.0f / (1.0f + __expf(-f));
    freq = 440.0f * exp2f((uf * MIDI_MAX - 69.0f) * (1.0f / 12.0f));

    float sa = 1.0f / (1.0f + __expf(-a));
    float am = 2.0f * __expf(LOG10_F * __logf(sa)) + 1e-7f;

    float aa = ((freq * h < NYQ) ? 1.0f : 0.0f) + 1e-4f;
    amp = am * aa;
}

// ---------------------------------------------------------------------------
// Single fused kernel, BARRIER-FREE and SMEM-FREE.
//
// One block per segment (b, j), 400 threads. Thread tid owns fixed channel
// float4-group c4 = tid % 25 and base row r0 = tid / 25 (0..15).
//
// Each thread loads ITS OWN endpoint data (4x LDG.128, L1-broadcast across
// the 16 threads sharing c4) and applies controls math to its 8 elements in
// registers — no staging, no __syncthreads. Threads with r0 == 0 write the
// segment's frequency outputs (one float4 each, 25 threads x 4 ch = 100).
//
// Store phase: d = x1 - x0, then 16 fully coalesced float4 stores
// (iteration k -> float4 index seg*6400 + 400k + tid, row 16k + r0) with
// dependence-free closed-form hann weights:
//   w_k = 0.5 - HC[k]*c0 + HS[k]*s0, (c0,s0) = cos/sin(pi*r0/256),
//   HC[k] = 0.5*cos(k*pi/16), HS[k] = 0.5*sin(k*pi/16) immediates.
// ---------------------------------------------------------------------------
__global__ __launch_bounds__(UP_THREADS) void synth_kernel(
        const float4* __restrict__ amp_in,
        const float4* __restrict__ freq_in,
        float4* __restrict__ out,
        float4* __restrict__ freq_out) {
    const int tid = threadIdx.x;
    const int seg = blockIdx.x;

    int segn = seg + 1;
    if (segn % FRAMES == 0) segn = seg;       // clamp: frame 250 == frame 249

    const int c4 = tid % 25;                  // channel float4-group (fixed)
    const int r0 = tid / 25;                  // base row (0..15)

    // Endpoint raw data — issue all 4 wide loads up front.
    const float4 a0 = amp_in [seg  * CH4 + c4];
    const float4 a1 = amp_in [segn * CH4 + c4];
    const float4 f0 = freq_in[seg  * CH4 + c4];
    const float4 f1 = freq_in[segn * CH4 + c4];

    // Base angle + immediates for the window closed form (overlaps loads).
    float c0, s0;
    sincospif((float)r0 * (1.0f / 256.0f), &s0, &c0);

    const float HC[STORES] = {
         0.5000000000f,  0.4903926402f,  0.4619397663f,  0.4157348062f,
         0.3535533906f,  0.2777851165f,  0.1913417162f,  0.0975451610f,
         0.0000000000f, -0.0975451610f, -0.1913417162f, -0.2777851165f,
        -0.3535533906f, -0.4157348062f, -0.4619397663f, -0.4903926402f };
    const float HS[STORES] = {
         0.0000000000f,  0.0975451610f,  0.1913417162f,  0.2777851165f,
         0.3535533906f,  0.4157348062f,  0.4619397663f,  0.4903926402f,
         0.5000000000f,  0.4903926402f,  0.4619397663f,  0.4157348062f,
         0.3535533906f,  0.2777851165f,  0.1913417162f,  0.0975451610f };

    // Controls for the 8 owned elements (4 channels x 2 endpoints).
    const float hb = (float)(c4 * 4);         // harmonic base (h = hb + 1..4)
    float4 x0, x1, fr0, fr1;
    ctrl1(a0.x, f0.x, hb + 1.0f, x0.x, fr0.x);
    ctrl1(a0.y, f0.y, hb + 2.0f, x0.y, fr0.y);
    ctrl1(a0.z, f0.z, hb + 3.0f, x0.z, fr0.z);
    ctrl1(a0.w, f0.w, hb + 4.0f, x0.w, fr0.w);
    ctrl1(a1.x, f1.x, hb + 1.0f, x1.x, fr1.x);
    ctrl1(a1.y, f1.y, hb + 2.0f, x1.y, fr1.y);
    ctrl1(a1.z, f1.z, hb + 3.0f, x1.z, fr1.z);
    ctrl1(a1.w, f1.w, hb + 4.0f, x1.w, fr1.w);

    // Frequency output: once per segment, by the r0 == 0 threads.
    if (r0 == 0) {
        freq_out[seg * CH4 + c4] = fr0;
    }

    float4 d;
    d.x = x1.x - x0.x;
    d.y = x1.y - x0.y;
    d.z = x1.z - x0.z;
    d.w = x1.w - x0.w;

    float4* o = out + (size_t)seg * SEG_VEC4 + tid;

#pragma unroll
    for (int k = 0; k < STORES; k++) {
        // w = 0.5 - HC[k]*c0 + HS[k]*s0  (independent per k)
        const float w = fmaf(HS[k], s0, fmaf(-HC[k], c0, 0.5f));
        float4 v;
        v.x = fmaf(d.x, w, x0.x);
        v.y = fmaf(d.y, w, x0.y);
        v.z = fmaf(d.z, w, x0.z);
        v.w = fmaf(d.w, w, x0.w);
        o[UP_THREADS * k] = v;
    }
}

// ---------------------------------------------------------------------------
extern "C" void kernel_launch(void* const* d_in, const int* in_sizes, int n_in,
                              void* d_out, int out_size) {
    const float4* amps  = (const float4*)d_in[0];
    const float4* freqs = (const float4*)d_in[1];
    float* out = (float*)d_out;

    synth_kernel<<<SEGS, UP_THREADS>>>(amps, freqs, (float4*)out,
                                       (float4*)(out + ENV_ELEMS));
}